// round 10
// baseline (speedup 1.0000x reference)
#include <cuda_runtime.h>
#include <cuda_bf16.h>
#include <math.h>

// Problem constants (fixed by setup_inputs): B=8, T=200, U=100, V=512
#define B_   8
#define T_   200
#define U_   100
#define U1_  101
#define V_   512
#define RSTR 102            // padded row stride for blank/emit tables
#define NEG  (-1.0e30f)     // effective -inf without NaN hazards

#define N_WORKER_BLK 20200  // 161600 rows / 8 warps per block
#define N_BLK (B_ + N_WORKER_BLK)

// Scratch (device globals — allocation-free rule)
__device__ float    g_blank[B_ * T_ * RSTR]; // log P(blank | b,t,u)
__device__ float    g_emit [B_ * T_ * RSTR]; // log P(label[u]|b,t,u)
__device__ float    g_costs[B_];
__device__ unsigned g_rowcnt[B_ * T_];       // cells completed per (b,t); reset by alpha blocks
__device__ unsigned g_done = 0;

__device__ __forceinline__ unsigned ld_acquire_u32(const unsigned* p) {
    unsigned v;
    asm volatile("ld.acquire.gpu.global.u32 %0, [%1];" : "=r"(v) : "l"(p) : "memory");
    return v;
}
__device__ __forceinline__ void red_release_add_u32(unsigned* p, unsigned v) {
    asm volatile("red.release.gpu.global.add.u32 [%0], %1;" :: "l"(p), "r"(v) : "memory");
}

// ---------------------------------------------------------------------------
// Fused kernel. Blocks 0..7: alpha wavefront (one batch each, wave-1 resident,
// spin on row counters). Blocks 8..: LSE workers (one warp per (t,b,u) row,
// t-major so production order matches wavefront consumption order).
// ---------------------------------------------------------------------------
__global__ __launch_bounds__(256, 3)
void rnnt_fused(const float* __restrict__ acts,
                const int*   __restrict__ labels,
                const int*   __restrict__ act_lens,
                const int*   __restrict__ label_lens,
                float*       __restrict__ out)
{
    if (blockIdx.x >= B_) {
        // =================== worker role: log-softmax over V=512 ===========
        const int wid  = threadIdx.x >> 5;
        const int lane = threadIdx.x & 31;
        const int W = (blockIdx.x - B_) * 8 + wid;      // 0 .. 161599
        // t-major enumeration: all batches' row t finish together
        const int t = W / (B_ * U1_);
        const int r = W % (B_ * U1_);
        const int b = r / U1_;
        const int u = r % U1_;
        const int arow = (b * T_ + t) * U1_ + u;

        const float4* rp = reinterpret_cast<const float4*>(acts + (size_t)arow * V_);
        float4 v0 = rp[lane +  0];
        float4 v1 = rp[lane + 32];
        float4 v2 = rp[lane + 64];
        float4 v3 = rp[lane + 96];

        float m = fmaxf(fmaxf(fmaxf(v0.x, v0.y), fmaxf(v0.z, v0.w)),
                        fmaxf(fmaxf(v1.x, v1.y), fmaxf(v1.z, v1.w)));
        m = fmaxf(m, fmaxf(fmaxf(fmaxf(v2.x, v2.y), fmaxf(v2.z, v2.w)),
                           fmaxf(fmaxf(v3.x, v3.y), fmaxf(v3.z, v3.w))));
        #pragma unroll
        for (int off = 16; off > 0; off >>= 1)
            m = fmaxf(m, __shfl_xor_sync(0xFFFFFFFFu, m, off));

        float s = __expf(v0.x-m) + __expf(v0.y-m) + __expf(v0.z-m) + __expf(v0.w-m)
                + __expf(v1.x-m) + __expf(v1.y-m) + __expf(v1.z-m) + __expf(v1.w-m)
                + __expf(v2.x-m) + __expf(v2.y-m) + __expf(v2.z-m) + __expf(v2.w-m)
                + __expf(v3.x-m) + __expf(v3.y-m) + __expf(v3.z-m) + __expf(v3.w-m);
        #pragma unroll
        for (int off = 16; off > 0; off >>= 1)
            s += __shfl_xor_sync(0xFFFFFFFFu, s, off);

        if (lane == 0) {
            const float lse = m + __logf(s);
            const int base = (b * T_ + t) * RSTR + u;
            g_blank[base] = v0.x - lse;                 // acts[arow][0]
            if (u < U_) {
                int lab = labels[b * U_ + u];
                lab = min(max(lab, 0), V_ - 1);
                g_emit[base] = acts[(size_t)arow * V_ + lab] - lse;
            }
            red_release_add_u32(&g_rowcnt[b * T_ + t], 1u);  // release: data before flag
        }
        return;
    }

    // =================== alpha role: wavefront for batch b =================
    __shared__ float row_a[2][T_ + 8];
    __shared__ float cost_sh;

    const int b    = blockIdx.x;
    const int Tb   = act_lens[b];
    const int Ub   = label_lens[b];
    const int tid  = threadIdx.x;
    const int w    = tid >> 5;
    const int lane = tid & 31;
    const int t    = 24 * w + lane;                 // 0..199, 8-row warp overlap

    const float*    rowb   = g_blank + (b * T_ + t) * RSTR;
    const float*    rowe   = g_emit  + (b * T_ + t) * RSTR;
    const unsigned* myflag = &g_rowcnt[b * T_ + t];

    float a = NEG;
    const int ndiag   = Tb + Ub;                    // diagonals d = 0..ndiag-1
    const int ngroups = (ndiag + 7) >> 3;
    bool waited = false;
    int  parity = 0;

    for (int g = 0; g < ngroups; ++g) {
        const int d_end = 8 * g + 7;
        // wait for own row before first group that can touch it
        if (!waited && t <= d_end) {
            while (ld_acquire_u32(myflag) < (unsigned)U1_) __nanosleep(128);
            waited = true;
        }
        // load this group's blank/emit window into registers (off the chain)
        const int u0 = 8 * g - 1 - t;               // u_old at step k=0
        float blv[8], emv[8];
        #pragma unroll
        for (int k = 0; k < 8; ++k) {
            const int ci = min(max(u0 + k, 0), 100);
            blv[k] = rowb[ci];
            emv[k] = rowe[min(ci, 99)];
        }
        #pragma unroll
        for (int k = 0; k < 8; ++k) {
            const float sv = a + blv[k];            // sender: alpha(t,u_old)+blank(t,u_old)
            float rr = __shfl_up_sync(0xFFFFFFFFu, sv, 1);
            if (lane == 0) rr = NEG;                // w==0: no t-1; w>0: halo (stale by design)
            const float vv = a + emv[k];

            const float hi = fmaxf(rr, vv);
            const float lo = fminf(rr, vv);
            const float val = hi + __logf(1.0f + __expf(lo - hi));

            const int u_new = u0 + k + 1;           // = d - t
            a = (u_new >= 0 && u_new <= Ub) ? val : NEG;
            if (t == 0 && u_new == 0) a = 0.0f;     // alpha[0,0] = 0

            if (u_new == Ub && t == Tb - 1 && (w == 0 || lane > k))
                cost_sh = -(a + blv[0] * 0.0f - 0.0f + rowb[Ub]);
            // (rowb[Ub] is L1-hot; expression kept simple: -(a + rowb[Ub]))
        }
        // halo refresh every 8 steps
        if (w == 0 || lane >= 8) row_a[parity][t] = a;
        __syncthreads();
        if (w > 0 && lane < 8) a = row_a[parity][t];
        parity ^= 1;
    }

    __syncthreads();
    // make sure ALL rows of this batch were produced (high-t rows may never
    // have been waited on), then reset counters for the next graph replay
    for (int i = tid; i < T_; i += 256)
        while (ld_acquire_u32(&g_rowcnt[b * T_ + i]) < (unsigned)U1_) __nanosleep(128);
    __syncthreads();
    for (int i = tid; i < T_; i += 256) g_rowcnt[b * T_ + i] = 0;
    __threadfence();

    if (tid == 0) {
        g_costs[b] = cost_sh;
        __threadfence();
        const unsigned r = atomicAdd(&g_done, 1u);
        if (r == B_ - 1) {                          // last alpha block: final sum
            __threadfence();
            float ssum = 0.0f;
            #pragma unroll
            for (int i = 0; i < B_; ++i) ssum += g_costs[i];
            out[0] = ssum;
            g_done = 0;                             // reset for next replay
        }
    }
}

extern "C" void kernel_launch(void* const* d_in, const int* in_sizes, int n_in,
                              void* d_out, int out_size)
{
    const float* acts       = (const float*)d_in[0];
    const int*   labels     = (const int*)d_in[1];   // int32 (JAX x64 disabled)
    const int*   act_lens   = (const int*)d_in[2];
    const int*   label_lens = (const int*)d_in[3];
    float*       out        = (float*)d_out;

    rnnt_fused<<<N_BLK, 256>>>(acts, labels, act_lens, label_lens, out);
}

// round 11
// speedup vs baseline: 1.0053x; 1.0053x over previous
#include <cuda_runtime.h>
#include <cuda_bf16.h>
#include <math.h>

// Problem constants (fixed by setup_inputs): B=8, T=200, U=100, V=512
#define B_   8
#define T_   200
#define U_   100
#define U1_  101
#define V_   512
#define RSTR 102            // padded row stride for blank/emit tables
#define NEG  (-1.0e30f)     // effective -inf without NaN hazards

#define N_WORKER_BLK 20200  // 161600 rows / 8 warps per block
#define N_BLK (B_ + N_WORKER_BLK)

// Scratch (device globals — allocation-free rule)
__device__ float    g_blank[B_ * T_ * RSTR]; // log P(blank | b,t,u)
__device__ float    g_emit [B_ * T_ * RSTR]; // log P(label[u]|b,t,u)
__device__ float    g_costs[B_];
__device__ unsigned g_rowcnt[B_ * T_];       // cells completed per (b,t); reset by alpha blocks
__device__ unsigned g_done = 0;

__device__ __forceinline__ unsigned ld_acquire_u32(const unsigned* p) {
    unsigned v;
    asm volatile("ld.acquire.gpu.global.u32 %0, [%1];" : "=r"(v) : "l"(p) : "memory");
    return v;
}
__device__ __forceinline__ void red_release_add_u32(unsigned* p, unsigned v) {
    asm volatile("red.release.gpu.global.add.u32 [%0], %1;" :: "l"(p), "r"(v) : "memory");
}

// ---------------------------------------------------------------------------
// Fused kernel. Blocks 0..7: alpha wavefront (one batch each, wave-1 resident,
// spin on row counters). Blocks 8..: LSE workers (one warp per (t,b,u) row,
// t-major so production order matches wavefront consumption order).
// ---------------------------------------------------------------------------
__global__ __launch_bounds__(256, 3)
void rnnt_fused(const float* __restrict__ acts,
                const int*   __restrict__ labels,
                const int*   __restrict__ act_lens,
                const int*   __restrict__ label_lens,
                float*       __restrict__ out)
{
    if (blockIdx.x >= B_) {
        // =================== worker role: log-softmax over V=512 ===========
        const int wid  = threadIdx.x >> 5;
        const int lane = threadIdx.x & 31;
        const int W = (blockIdx.x - B_) * 8 + wid;      // 0 .. 161599
        // t-major enumeration: all batches' row t finish together
        const int t = W / (B_ * U1_);
        const int r = W % (B_ * U1_);
        const int b = r / U1_;
        const int u = r % U1_;
        const int arow = (b * T_ + t) * U1_ + u;

        const float4* rp = reinterpret_cast<const float4*>(acts + (size_t)arow * V_);
        float4 v0 = rp[lane +  0];
        float4 v1 = rp[lane + 32];
        float4 v2 = rp[lane + 64];
        float4 v3 = rp[lane + 96];

        float m = fmaxf(fmaxf(fmaxf(v0.x, v0.y), fmaxf(v0.z, v0.w)),
                        fmaxf(fmaxf(v1.x, v1.y), fmaxf(v1.z, v1.w)));
        m = fmaxf(m, fmaxf(fmaxf(fmaxf(v2.x, v2.y), fmaxf(v2.z, v2.w)),
                           fmaxf(fmaxf(v3.x, v3.y), fmaxf(v3.z, v3.w))));
        #pragma unroll
        for (int off = 16; off > 0; off >>= 1)
            m = fmaxf(m, __shfl_xor_sync(0xFFFFFFFFu, m, off));

        float s = __expf(v0.x-m) + __expf(v0.y-m) + __expf(v0.z-m) + __expf(v0.w-m)
                + __expf(v1.x-m) + __expf(v1.y-m) + __expf(v1.z-m) + __expf(v1.w-m)
                + __expf(v2.x-m) + __expf(v2.y-m) + __expf(v2.z-m) + __expf(v2.w-m)
                + __expf(v3.x-m) + __expf(v3.y-m) + __expf(v3.z-m) + __expf(v3.w-m);
        #pragma unroll
        for (int off = 16; off > 0; off >>= 1)
            s += __shfl_xor_sync(0xFFFFFFFFu, s, off);

        if (lane == 0) {
            const float lse = m + __logf(s);
            const int base = (b * T_ + t) * RSTR + u;
            g_blank[base] = v0.x - lse;                 // acts[arow][0]
            if (u < U_) {
                int lab = labels[b * U_ + u];
                lab = min(max(lab, 0), V_ - 1);
                g_emit[base] = acts[(size_t)arow * V_ + lab] - lse;
            }
            red_release_add_u32(&g_rowcnt[b * T_ + t], 1u);  // release: data before flag
        }
        return;
    }

    // =================== alpha role: wavefront for batch b =================
    __shared__ float row_a[2][T_ + 8];
    __shared__ float cost_sh;

    const int b    = blockIdx.x;
    const int Tb   = act_lens[b];
    const int Ub   = label_lens[b];
    const int tid  = threadIdx.x;
    const int w    = tid >> 5;
    const int lane = tid & 31;
    const int t    = 24 * w + lane;                 // 0..199, 8-row warp overlap

    const float*    rowb   = g_blank + (b * T_ + t) * RSTR;
    const float*    rowe   = g_emit  + (b * T_ + t) * RSTR;
    const unsigned* myflag = &g_rowcnt[b * T_ + t];

    float a = NEG;
    const int ndiag   = Tb + Ub;                    // diagonals d = 0..ndiag-1
    const int ngroups = (ndiag + 7) >> 3;
    bool waited = false;
    int  parity = 0;

    for (int g = 0; g < ngroups; ++g) {
        const int d_end = 8 * g + 7;
        // wait for own row before first group that can touch it
        if (!waited && t <= d_end) {
            while (ld_acquire_u32(myflag) < (unsigned)U1_) __nanosleep(128);
            waited = true;
        }
        // load this group's blank/emit window into registers (off the chain)
        const int u0 = 8 * g - 1 - t;               // u_old at step k=0
        float blv[8], emv[8];
        #pragma unroll
        for (int k = 0; k < 8; ++k) {
            const int ci = min(max(u0 + k, 0), 100);
            blv[k] = rowb[ci];
            emv[k] = rowe[min(ci, 99)];
        }
        #pragma unroll
        for (int k = 0; k < 8; ++k) {
            const float sv = a + blv[k];            // sender: alpha(t,u_old)+blank(t,u_old)
            float rr = __shfl_up_sync(0xFFFFFFFFu, sv, 1);
            if (lane == 0) rr = NEG;                // w==0: no t-1; w>0: halo (stale by design)
            const float vv = a + emv[k];

            const float hi = fmaxf(rr, vv);
            const float lo = fminf(rr, vv);
            const float val = hi + __logf(1.0f + __expf(lo - hi));

            const int u_new = u0 + k + 1;           // = d - t
            a = (u_new >= 0 && u_new <= Ub) ? val : NEG;
            if (t == 0 && u_new == 0) a = 0.0f;     // alpha[0,0] = 0

            if (u_new == Ub && t == Tb - 1 && (w == 0 || lane > k))
                cost_sh = -(a + blv[0] * 0.0f - 0.0f + rowb[Ub]);
            // (rowb[Ub] is L1-hot; expression kept simple: -(a + rowb[Ub]))
        }
        // halo refresh every 8 steps
        if (w == 0 || lane >= 8) row_a[parity][t] = a;
        __syncthreads();
        if (w > 0 && lane < 8) a = row_a[parity][t];
        parity ^= 1;
    }

    __syncthreads();
    // make sure ALL rows of this batch were produced (high-t rows may never
    // have been waited on), then reset counters for the next graph replay
    for (int i = tid; i < T_; i += 256)
        while (ld_acquire_u32(&g_rowcnt[b * T_ + i]) < (unsigned)U1_) __nanosleep(128);
    __syncthreads();
    for (int i = tid; i < T_; i += 256) g_rowcnt[b * T_ + i] = 0;
    __threadfence();

    if (tid == 0) {
        g_costs[b] = cost_sh;
        __threadfence();
        const unsigned r = atomicAdd(&g_done, 1u);
        if (r == B_ - 1) {                          // last alpha block: final sum
            __threadfence();
            float ssum = 0.0f;
            #pragma unroll
            for (int i = 0; i < B_; ++i) ssum += g_costs[i];
            out[0] = ssum;
            g_done = 0;                             // reset for next replay
        }
    }
}

extern "C" void kernel_launch(void* const* d_in, const int* in_sizes, int n_in,
                              void* d_out, int out_size)
{
    const float* acts       = (const float*)d_in[0];
    const int*   labels     = (const int*)d_in[1];   // int32 (JAX x64 disabled)
    const int*   act_lens   = (const int*)d_in[2];
    const int*   label_lens = (const int*)d_in[3];
    float*       out        = (float*)d_out;

    rnnt_fused<<<N_BLK, 256>>>(acts, labels, act_lens, label_lens, out);
}